// round 10
// baseline (speedup 1.0000x reference)
#include <cuda_runtime.h>
#include <cuda_fp16.h>
#include <cstdint>
#include <cstddef>

#define NROWS 4096
#define ODIM  512
#define IDIM  512
#define DDIM  64

#define BM 128
#define BN 64
#define NTH 256
#define NT_W 256            // W tiles, each covering 2 consecutive i (BK = 128)
#define NTILES 257          // + bias half-tile

#define BPITCHB 272u                       // 68 words ≡ 4 mod 32 -> ldmatrix 8-row conflict-free
#define B_STAGE (64u * BPITCHB)            // 17408 B
#define V_OFF   (4u * B_STAGE)             // 69632
#define VPITCHB 160u                       // 40 words ≡ 8 mod 32 -> LDS.64 conflict-free
#define SMEM_TOTAL (int)(V_OFF + 128u * VPITCHB)   // 90112 B -> 2 CTAs/SM

__device__ float  g_xT[IDIM * NROWS];                  // x transposed: [512][4096] fp32
__device__ __half g_Wt[(size_t)IDIM * ODIM * DDIM];    // W re-laid: [i][o][d] fp16 (natural d)
__device__ __half g_bt[ODIM * DDIM];                   // b1 re-laid: [o][d] fp16 (natural d)

// var pair-permutation within groups of 8 pairs: logical j -> phys (j<4 ? 2j : 2(j-4)+1)
__device__ __forceinline__ int pperm(int pr) {
    int gq = pr >> 3, j = pr & 7;
    int pj = (j < 4) ? (2 * j) : (2 * (j - 4) + 1);
    return gq * 8 + pj;
}

// ---------------- helpers ----------------
__device__ __forceinline__ uint32_t smem_u32(const void* p) {
    uint32_t a;
    asm("{ .reg .u64 t; cvta.to.shared.u64 t, %1; cvt.u32.u64 %0, t; }" : "=r"(a) : "l"(p));
    return a;
}
__device__ __forceinline__ uint32_t f2h2(float f) {   // (h,h) packed fp16x2
    uint32_t r;
    asm("{ .reg .b16 h; cvt.rn.f16.f32 h, %1; mov.b32 %0, {h, h}; }" : "=r"(r) : "f"(f));
    return r;
}
#define CP_ASYNC16(dst, src) \
    asm volatile("cp.async.cg.shared.global [%0], [%1], 16;" :: "r"(dst), "l"(src) : "memory")
#define CP_COMMIT() asm volatile("cp.async.commit_group;" ::: "memory")
#define CP_WAIT2()  asm volatile("cp.async.wait_group 2;" ::: "memory")

#define LDS64(lo, hi, a) \
    asm volatile("ld.shared.v2.b32 {%0, %1}, [%2];" : "=r"(lo), "=r"(hi) : "r"(a))
#define LDMX4(r0, r1, r2, r3, a) \
    asm volatile("ldmatrix.sync.aligned.m8n8.x4.shared.b16 {%0,%1,%2,%3}, [%4];" \
        : "=r"(r0), "=r"(r1), "=r"(r2), "=r"(r3) : "r"(a))
#define HMUL2(d, a, b) asm("mul.rn.f16x2 %0, %1, %2;" : "=r"(d) : "r"(a), "r"(b))

__device__ __forceinline__ void mma_f16_16816(float& c0, float& c1, float& c2, float& c3,
                                              uint32_t a0, uint32_t a1, uint32_t a2, uint32_t a3,
                                              uint32_t b0, uint32_t b1) {
    asm volatile(
        "mma.sync.aligned.m16n8k16.row.col.f32.f16.f16.f32 "
        "{%0,%1,%2,%3}, {%4,%5,%6,%7}, {%8,%9}, {%0,%1,%2,%3};"
        : "+f"(c0), "+f"(c1), "+f"(c2), "+f"(c3)
        : "r"(a0), "r"(a1), "r"(a2), "r"(a3), "r"(b0), "r"(b1));
}

// ---------------- prepass kernels ----------------
__global__ void __launch_bounds__(1024) transpose_x(const float* __restrict__ x) {
    __shared__ float t[32][33];
    const int bi = blockIdx.x * 32;
    const int bn = blockIdx.y * 32;
    t[threadIdx.y][threadIdx.x] = x[(size_t)(bn + threadIdx.y) * IDIM + bi + threadIdx.x];
    __syncthreads();
    g_xT[(size_t)(bi + threadIdx.y) * NROWS + bn + threadIdx.x] = t[threadIdx.x][threadIdx.y];
}

// W[d][i][o] fp32 -> g_Wt[i][o][d] fp16 (natural d order; ldmatrix handles distribution)
__global__ void __launch_bounds__(1024) prep_w(const float* __restrict__ W) {
    __shared__ float sm[32][65];
    const int i  = blockIdx.x;
    const int ob = blockIdx.y * 32;
    const int tx = threadIdx.x, ty = threadIdx.y;
#pragma unroll
    for (int k = 0; k < 2; ++k) {
        int d = ty + k * 32;
        sm[tx][d] = W[(size_t)d * IDIM * ODIM + (size_t)i * ODIM + ob + tx];
    }
    __syncthreads();
    __half2 h = __floats2half2_rn(sm[ty][2 * tx], sm[ty][2 * tx + 1]);
    reinterpret_cast<__half2*>(g_Wt)[((size_t)i * ODIM + ob + ty) * 32 + tx] = h;
}

// b1[d][o] fp32 -> g_bt[o][d] fp16 (natural)
__global__ void __launch_bounds__(1024) prep_b(const float* __restrict__ b1) {
    __shared__ float sm[32][65];
    const int ob = blockIdx.x * 32;
    const int tx = threadIdx.x, ty = threadIdx.y;
#pragma unroll
    for (int k = 0; k < 2; ++k) {
        int d = ty + k * 32;
        sm[tx][d] = b1[(size_t)d * ODIM + ob + tx];
    }
    __syncthreads();
    __half2 h = __floats2half2_rn(sm[ty][2 * tx], sm[ty][2 * tx + 1]);
    reinterpret_cast<__half2*>(g_bt)[(size_t)(ob + ty) * 32 + tx] = h;
}

// ---------------- main kernel ----------------
__global__ void __launch_bounds__(NTH, 2) mlp_mma(
    const float* __restrict__ var,
    float* __restrict__ out)
{
    extern __shared__ __align__(128) uint8_t smem[];
    const uint32_t s0 = smem_u32(smem);
    const uint32_t vS = s0 + V_OFF;

    const int tid  = threadIdx.x;
    const int lane = tid & 31;
    const int w    = tid >> 5;
    const int rowBase = blockIdx.y * BM;
    const int colBase = blockIdx.x * BN;

    const int wm = (w & 3) * 32;    // warp m-base (4 warps over M)
    const int wn = (w >> 2) * 32;   // warp n-base (2 warps over N)
    const int c  = lane & 3;
    const int g  = lane >> 2;

    // ----- stage var as fp16x2 pairs (permuted): vh[m][pperm(d/2)], pitch 160B -----
    for (int idx = tid; idx < BM * 32; idx += NTH) {
        int m = idx >> 5, pr = idx & 31;
        float2 vv = *reinterpret_cast<const float2*>(&var[(size_t)(rowBase + m) * DDIM + 2 * pr]);
        __half2 h = __floats2half2_rn(vv.x, vv.y);
        asm volatile("st.shared.b32 [%0], %1;" ::
            "r"(vS + (uint32_t)m * VPITCHB + (uint32_t)pperm(pr) * 4u),
            "r"(*reinterpret_cast<uint32_t*>(&h)) : "memory");
    }

    // ----- this thread's 4 fragment rows -----
    int xr[4];
    uint32_t vAddr[4];
#pragma unroll
    for (int rr = 0; rr < 4; ++rr) {
        int mloc = wm + (rr >> 1) * 16 + (rr & 1) * 8 + g;
        xr[rr] = rowBase + mloc;
        vAddr[rr] = vS + (uint32_t)mloc * VPITCHB + (uint32_t)c * 8u;  // phys pair 2c
    }

    // ----- ldmatrix per-lane base: q = lane/8 selects (nt-block, k-octet) -----
    const int q = lane >> 3, r8 = lane & 7;
    const uint32_t bRowLd = (uint32_t)(wn + ((q >> 1) << 3) + r8) * BPITCHB
                          + (uint32_t)(q & 1) * 16u;

    // ----- B loader (cp.async): o-row = tid/4, two 16B chunks per 128B half -----
    const int bo = tid >> 2;
    const int ci = tid & 3;
    auto issueB = [&](int t) {
        const uint32_t dstBase = s0 + (uint32_t)(t & 3) * B_STAGE + (uint32_t)bo * BPITCHB;
        if (t < NT_W) {
            const __half* p0 = g_Wt + ((size_t)(2 * t) * ODIM + colBase + bo) * DDIM;
            const __half* p1 = p0 + (size_t)ODIM * DDIM;
#pragma unroll
            for (int cc = 0; cc < 2; ++cc) {
                uint32_t ch = (uint32_t)(ci + cc * 4);
                CP_ASYNC16(dstBase + ch * 16u,        p0 + ch * 8);
                CP_ASYNC16(dstBase + 128u + ch * 16u, p1 + ch * 8);
            }
        } else {   // bias half-tile: k 0..63 only; k 64..127 stale (annihilated by x=0)
            const __half* p0 = g_bt + (size_t)(colBase + bo) * DDIM;
#pragma unroll
            for (int cc = 0; cc < 2; ++cc) {
                uint32_t ch = (uint32_t)(ci + cc * 4);
                CP_ASYNC16(dstBase + ch * 16u, p0 + ch * 8);
            }
        }
        CP_COMMIT();
    };
    auto loadX = [&](int t, float* a0, float* a1) {
        if (t < NT_W) {
#pragma unroll
            for (int rr = 0; rr < 4; ++rr) {
                a0[rr] = __ldg(&g_xT[(size_t)(2 * t) * NROWS + xr[rr]]);
                a1[rr] = __ldg(&g_xT[(size_t)(2 * t + 1) * NROWS + xr[rr]]);
            }
        } else {
#pragma unroll
            for (int rr = 0; rr < 4; ++rr) { a0[rr] = (t == NT_W) ? 1.0f : 0.0f; a1[rr] = 0.0f; }
        }
    };

    float C[2][4][4];
#pragma unroll
    for (int mt = 0; mt < 2; ++mt)
#pragma unroll
        for (int nt = 0; nt < 4; ++nt)
#pragma unroll
            for (int qq = 0; qq < 4; ++qq) C[mt][nt][qq] = 0.0f;

    // ----- prologue -----
    issueB(0); issueB(1); issueB(2);
    float xc0[4], xc1[4], xn0[4], xn1[4];
    loadX(0, xc0, xc1);
    __syncthreads();   // vh ready

    // ----- mainloop: one __syncthreads per tile -----
    for (int i = 0; i < NTILES; ++i) {
        CP_WAIT2();
        __syncthreads();

        if (i + 3 <= NT_W) issueB(i + 3);
        else CP_COMMIT();             // keep group accounting so WAIT2 lands tile i
        loadX(i + 1, xn0, xn1);

        uint32_t xh[2][4];
#pragma unroll
        for (int rr = 0; rr < 4; ++rr) {
            xh[0][rr] = f2h2(xc0[rr]);
            xh[1][rr] = f2h2(xc1[rr]);
        }

        const uint32_t bB0 = s0 + (uint32_t)(i & 3) * B_STAGE + bRowLd;

#pragma unroll
        for (int grp = 0; grp < 4; ++grp) {
            // v pairs for this d-group: hoisted, reused by both il (d independent of i)
            uint32_t v[4][2];
#pragma unroll
            for (int rr = 0; rr < 4; ++rr)
                LDS64(v[rr][0], v[rr][1], vAddr[rr] + (uint32_t)grp * 32u);

#pragma unroll
            for (int il = 0; il < 2; ++il) {
                const int ks = il * 4 + grp;
                // B fragments: 2 x ldmatrix.x4 cover nt 0..3 (both k-octets each)
                uint32_t b[4][2];
                LDMX4(b[0][0], b[0][1], b[1][0], b[1][1], bB0 + (uint32_t)ks * 32u);
                LDMX4(b[2][0], b[2][1], b[3][0], b[3][1],
                      bB0 + (uint32_t)ks * 32u + 16u * BPITCHB);
                // A fragments
                uint32_t a[2][4];
#pragma unroll
                for (int mt = 0; mt < 2; ++mt) {
                    HMUL2(a[mt][0], xh[il][mt * 2 + 0], v[mt * 2 + 0][0]);
                    HMUL2(a[mt][1], xh[il][mt * 2 + 1], v[mt * 2 + 1][0]);
                    HMUL2(a[mt][2], xh[il][mt * 2 + 0], v[mt * 2 + 0][1]);
                    HMUL2(a[mt][3], xh[il][mt * 2 + 1], v[mt * 2 + 1][1]);
                }
#pragma unroll
                for (int mt = 0; mt < 2; ++mt)
#pragma unroll
                    for (int nt = 0; nt < 4; ++nt)
                        mma_f16_16816(C[mt][nt][0], C[mt][nt][1], C[mt][nt][2], C[mt][nt][3],
                                      a[mt][0], a[mt][1], a[mt][2], a[mt][3],
                                      b[nt][0], b[nt][1]);
            }
        }

#pragma unroll
        for (int rr = 0; rr < 4; ++rr) { xc0[rr] = xn0[rr]; xc1[rr] = xn1[rr]; }
    }

    // ----- epilogue -----
#pragma unroll
    for (int mt = 0; mt < 2; ++mt) {
        const int r0 = rowBase + wm + mt * 16 + g;
#pragma unroll
        for (int nt = 0; nt < 4; ++nt) {
            const int c0i = colBase + wn + nt * 8 + c * 2;
            float2 v0, v1;
            v0.x = C[mt][nt][0]; v0.y = C[mt][nt][1];
            v1.x = C[mt][nt][2]; v1.y = C[mt][nt][3];
            *reinterpret_cast<float2*>(&out[(size_t)r0 * ODIM + c0i]) = v0;
            *reinterpret_cast<float2*>(&out[(size_t)(r0 + 8) * ODIM + c0i]) = v1;
        }
    }
}

// ---------------- host ----------------
extern "C" void kernel_launch(void* const* d_in, const int* in_sizes, int n_in,
                              void* d_out, int out_size) {
    const float* x   = (const float*)d_in[0];   // [4096, 512]
    const float* var = (const float*)d_in[1];   // [4096, 64]
    const float* W   = (const float*)d_in[2];   // [64, 512, 512]
    const float* b1  = (const float*)d_in[3];   // [64, 512]
    float* out       = (float*)d_out;           // [4096, 512]

    {
        dim3 tb(32, 32), tg(IDIM / 32, NROWS / 32);
        transpose_x<<<tg, tb>>>(x);
    }
    {
        dim3 tb(32, 32), tg(IDIM, ODIM / 32);
        prep_w<<<tg, tb>>>(W);
    }
    {
        dim3 tb(32, 32);
        prep_b<<<ODIM / 32, tb>>>(b1);
    }

    cudaFuncSetAttribute(mlp_mma, cudaFuncAttributeMaxDynamicSharedMemorySize, SMEM_TOTAL);
    dim3 grid(ODIM / BN, NROWS / BM);   // (8, 32) = 256 CTAs, 2 per SM
    mlp_mma<<<grid, NTH, SMEM_TOTAL>>>(var, out);
}

// round 11
// speedup vs baseline: 1.0499x; 1.0499x over previous
#include <cuda_runtime.h>
#include <cuda_fp16.h>
#include <cstdint>
#include <cstddef>

#define NROWS 4096
#define ODIM  512
#define IDIM  512
#define DDIM  64

#define BM 128
#define BN 64
#define NTH 256
#define NT_W 256            // W tiles, each covering 2 consecutive i (BK = 128)
#define NTILES 257          // + bias half-tile

#define BPITCHB 272u                       // 68 words ≡ 4 mod 32 -> ldmatrix 8-row conflict-free
#define B_STAGE (64u * BPITCHB)            // 17408 B
#define SMEM_TOTAL (int)(4u * B_STAGE)     // 69632 B -> 2 CTAs/SM easily

__device__ float  g_xT[IDIM * NROWS];                  // x transposed: [512][4096] fp32
__device__ __half g_Wt[(size_t)IDIM * ODIM * DDIM];    // W re-laid: [i][o][d] fp16
__device__ __half g_bt[ODIM * DDIM];                   // b1 re-laid: [o][d] fp16

// ---------------- helpers ----------------
__device__ __forceinline__ uint32_t smem_u32(const void* p) {
    uint32_t a;
    asm("{ .reg .u64 t; cvta.to.shared.u64 t, %1; cvt.u32.u64 %0, t; }" : "=r"(a) : "l"(p));
    return a;
}
__device__ __forceinline__ uint32_t f2h2(float f) {   // (h,h) packed fp16x2
    uint32_t r;
    asm("{ .reg .b16 h; cvt.rn.f16.f32 h, %1; mov.b32 %0, {h, h}; }" : "=r"(r) : "f"(f));
    return r;
}
__device__ __forceinline__ uint32_t pack2(float lo, float hi) {
    __half2 h = __floats2half2_rn(lo, hi);
    return *reinterpret_cast<uint32_t*>(&h);
}
#define CP_ASYNC16(dst, src) \
    asm volatile("cp.async.cg.shared.global [%0], [%1], 16;" :: "r"(dst), "l"(src) : "memory")
#define CP_COMMIT() asm volatile("cp.async.commit_group;" ::: "memory")
#define CP_WAIT2()  asm volatile("cp.async.wait_group 2;" ::: "memory")

#define LDMX4(r0, r1, r2, r3, a) \
    asm volatile("ldmatrix.sync.aligned.m8n8.x4.shared.b16 {%0,%1,%2,%3}, [%4];" \
        : "=r"(r0), "=r"(r1), "=r"(r2), "=r"(r3) : "r"(a))
#define HMUL2(d, a, b) asm("mul.rn.f16x2 %0, %1, %2;" : "=r"(d) : "r"(a), "r"(b))

__device__ __forceinline__ void mma_f16_16816(float& c0, float& c1, float& c2, float& c3,
                                              uint32_t a0, uint32_t a1, uint32_t a2, uint32_t a3,
                                              uint32_t b0, uint32_t b1) {
    asm volatile(
        "mma.sync.aligned.m16n8k16.row.col.f32.f16.f16.f32 "
        "{%0,%1,%2,%3}, {%4,%5,%6,%7}, {%8,%9}, {%0,%1,%2,%3};"
        : "+f"(c0), "+f"(c1), "+f"(c2), "+f"(c3)
        : "r"(a0), "r"(a1), "r"(a2), "r"(a3), "r"(b0), "r"(b1));
}

// ---------------- prepass kernels ----------------
__global__ void __launch_bounds__(1024) transpose_x(const float* __restrict__ x) {
    __shared__ float t[32][33];
    const int bi = blockIdx.x * 32;
    const int bn = blockIdx.y * 32;
    t[threadIdx.y][threadIdx.x] = x[(size_t)(bn + threadIdx.y) * IDIM + bi + threadIdx.x];
    __syncthreads();
    g_xT[(size_t)(bi + threadIdx.y) * NROWS + bn + threadIdx.x] = t[threadIdx.x][threadIdx.y];
}

// W[d][i][o] fp32 -> g_Wt[i][o][d] fp16
__global__ void __launch_bounds__(1024) prep_w(const float* __restrict__ W) {
    __shared__ float sm[32][65];
    const int i  = blockIdx.x;
    const int ob = blockIdx.y * 32;
    const int tx = threadIdx.x, ty = threadIdx.y;
#pragma unroll
    for (int k = 0; k < 2; ++k) {
        int d = ty + k * 32;
        sm[tx][d] = W[(size_t)d * IDIM * ODIM + (size_t)i * ODIM + ob + tx];
    }
    __syncthreads();
    __half2 h = __floats2half2_rn(sm[ty][2 * tx], sm[ty][2 * tx + 1]);
    reinterpret_cast<__half2*>(g_Wt)[((size_t)i * ODIM + ob + ty) * 32 + tx] = h;
}

// b1[d][o] fp32 -> g_bt[o][d] fp16
__global__ void __launch_bounds__(1024) prep_b(const float* __restrict__ b1) {
    __shared__ float sm[32][65];
    const int ob = blockIdx.x * 32;
    const int tx = threadIdx.x, ty = threadIdx.y;
#pragma unroll
    for (int k = 0; k < 2; ++k) {
        int d = ty + k * 32;
        sm[tx][d] = b1[(size_t)d * ODIM + ob + tx];
    }
    __syncthreads();
    __half2 h = __floats2half2_rn(sm[ty][2 * tx], sm[ty][2 * tx + 1]);
    reinterpret_cast<__half2*>(g_bt)[(size_t)(ob + ty) * 32 + tx] = h;
}

// ---------------- main kernel: v in registers, B double-buffered ----------------
__global__ void __launch_bounds__(NTH, 2) mlp_mma(
    const float* __restrict__ var,
    float* __restrict__ out)
{
    extern __shared__ __align__(128) uint8_t smem[];
    const uint32_t s0 = smem_u32(smem);

    const int tid  = threadIdx.x;
    const int lane = tid & 31;
    const int w    = tid >> 5;
    const int rowBase = blockIdx.y * BM;
    const int colBase = blockIdx.x * BN;

    const int wm = (w & 3) * 32;    // warp m-base (4 warps over M)
    const int wn = (w >> 2) * 32;   // warp n-base (2 warps over N)
    const int c  = lane & 3;
    const int g  = lane >> 2;

    // ----- this thread's 4 fragment rows -----
    int xr[4];
#pragma unroll
    for (int rr = 0; rr < 4; ++rr)
        xr[rr] = rowBase + wm + (rr >> 1) * 16 + (rr & 1) * 8 + g;

    // ----- v fragments in registers, loaded ONCE (v is tile-invariant) -----
    // vh[rr][grp][h]: fp16x2 pair for d = grp*16 + h*8 + {2c, 2c+1}
    uint32_t vh[4][4][2];
#pragma unroll
    for (int rr = 0; rr < 4; ++rr) {
        const float* vp = var + (size_t)xr[rr] * DDIM;
#pragma unroll
        for (int grp = 0; grp < 4; ++grp) {
            float2 p0 = *reinterpret_cast<const float2*>(vp + grp * 16 + 2 * c);
            float2 p1 = *reinterpret_cast<const float2*>(vp + grp * 16 + 8 + 2 * c);
            vh[rr][grp][0] = pack2(p0.x, p0.y);
            vh[rr][grp][1] = pack2(p1.x, p1.y);
        }
    }

    // ----- ldmatrix per-lane base: q = lane/8 selects (nt-block, k-octet) -----
    const int q = lane >> 3, r8 = lane & 7;
    const uint32_t bRowLd = (uint32_t)(wn + ((q >> 1) << 3) + r8) * BPITCHB
                          + (uint32_t)(q & 1) * 16u;

    // ----- B loader (cp.async): o-row = tid/4, two 16B chunks per 128B half -----
    const int bo = tid >> 2;
    const int ci = tid & 3;
    auto issueB = [&](int t) {
        const uint32_t dstBase = s0 + (uint32_t)(t & 3) * B_STAGE + (uint32_t)bo * BPITCHB;
        if (t < NT_W) {
            const __half* p0 = g_Wt + ((size_t)(2 * t) * ODIM + colBase + bo) * DDIM;
            const __half* p1 = p0 + (size_t)ODIM * DDIM;
#pragma unroll
            for (int cc = 0; cc < 2; ++cc) {
                uint32_t ch = (uint32_t)(ci + cc * 4);
                CP_ASYNC16(dstBase + ch * 16u,        p0 + ch * 8);
                CP_ASYNC16(dstBase + 128u + ch * 16u, p1 + ch * 8);
            }
        } else {   // bias half-tile: k 0..63 only; k 64..127 stale (annihilated by x=0)
            const __half* p0 = g_bt + (size_t)(colBase + bo) * DDIM;
#pragma unroll
            for (int cc = 0; cc < 2; ++cc) {
                uint32_t ch = (uint32_t)(ci + cc * 4);
                CP_ASYNC16(dstBase + ch * 16u, p0 + ch * 8);
            }
        }
        CP_COMMIT();
    };
    auto loadX = [&](int t, float* a0, float* a1) {
        if (t < NT_W) {
#pragma unroll
            for (int rr = 0; rr < 4; ++rr) {
                a0[rr] = __ldg(&g_xT[(size_t)(2 * t) * NROWS + xr[rr]]);
                a1[rr] = __ldg(&g_xT[(size_t)(2 * t + 1) * NROWS + xr[rr]]);
            }
        } else {
#pragma unroll
            for (int rr = 0; rr < 4; ++rr) { a0[rr] = (t == NT_W) ? 1.0f : 0.0f; a1[rr] = 0.0f; }
        }
    };

    float C[2][4][4];
#pragma unroll
    for (int mt = 0; mt < 2; ++mt)
#pragma unroll
        for (int nt = 0; nt < 4; ++nt)
#pragma unroll
            for (int qq = 0; qq < 4; ++qq) C[mt][nt][qq] = 0.0f;

    // ----- prologue -----
    issueB(0); issueB(1); issueB(2);
    float xc0[4], xc1[4], xn0[4], xn1[4];
    loadX(0, xc0, xc1);

    // ----- mainloop: one __syncthreads per tile -----
    for (int i = 0; i < NTILES; ++i) {
        CP_WAIT2();
        __syncthreads();

        if (i + 3 <= NT_W) issueB(i + 3);
        else CP_COMMIT();             // keep group accounting so WAIT2 lands tile i
        loadX(i + 1, xn0, xn1);

        uint32_t xh[2][4];
#pragma unroll
        for (int rr = 0; rr < 4; ++rr) {
            xh[0][rr] = f2h2(xc0[rr]);
            xh[1][rr] = f2h2(xc1[rr]);
        }

        const uint32_t bB0 = s0 + (uint32_t)(i & 3) * B_STAGE + bRowLd;

        // B double buffer across the 8 k-steps: kk = grp*2 + il, ks = il*4 + grp
        uint32_t bb[2][4][2];
        {   // prefetch kk = 0 (ks = 0)
            LDMX4(bb[0][0][0], bb[0][0][1], bb[0][1][0], bb[0][1][1], bB0);
            LDMX4(bb[0][2][0], bb[0][2][1], bb[0][3][0], bb[0][3][1], bB0 + 16u * BPITCHB);
        }

#pragma unroll
        for (int kk = 0; kk < 8; ++kk) {
            const int grp = kk >> 1, il = kk & 1;
            const int cur = kk & 1 ? 1 : 0;            // parity buffer
            if (kk < 7) {
                const int nk = kk + 1;
                const int nks = (nk & 1) * 4 + (nk >> 1);
                const int nxt = cur ^ 1;
                LDMX4(bb[nxt][0][0], bb[nxt][0][1], bb[nxt][1][0], bb[nxt][1][1],
                      bB0 + (uint32_t)nks * 32u);
                LDMX4(bb[nxt][2][0], bb[nxt][2][1], bb[nxt][3][0], bb[nxt][3][1],
                      bB0 + (uint32_t)nks * 32u + 16u * BPITCHB);
            }
            uint32_t a[2][4];
#pragma unroll
            for (int mt = 0; mt < 2; ++mt) {
                HMUL2(a[mt][0], xh[il][mt * 2 + 0], vh[mt * 2 + 0][grp][0]);
                HMUL2(a[mt][1], xh[il][mt * 2 + 1], vh[mt * 2 + 1][grp][0]);
                HMUL2(a[mt][2], xh[il][mt * 2 + 0], vh[mt * 2 + 0][grp][1]);
                HMUL2(a[mt][3], xh[il][mt * 2 + 1], vh[mt * 2 + 1][grp][1]);
            }
#pragma unroll
            for (int mt = 0; mt < 2; ++mt)
#pragma unroll
                for (int nt = 0; nt < 4; ++nt)
                    mma_f16_16816(C[mt][nt][0], C[mt][nt][1], C[mt][nt][2], C[mt][nt][3],
                                  a[mt][0], a[mt][1], a[mt][2], a[mt][3],
                                  bb[cur][nt][0], bb[cur][nt][1]);
        }

#pragma unroll
        for (int rr = 0; rr < 4; ++rr) { xc0[rr] = xn0[rr]; xc1[rr] = xn1[rr]; }
    }

    // ----- epilogue -----
#pragma unroll
    for (int mt = 0; mt < 2; ++mt) {
        const int r0 = rowBase + wm + mt * 16 + g;
#pragma unroll
        for (int nt = 0; nt < 4; ++nt) {
            const int c0i = colBase + wn + nt * 8 + c * 2;
            float2 v0, v1;
            v0.x = C[mt][nt][0]; v0.y = C[mt][nt][1];
            v1.x = C[mt][nt][2]; v1.y = C[mt][nt][3];
            *reinterpret_cast<float2*>(&out[(size_t)r0 * ODIM + c0i]) = v0;
            *reinterpret_cast<float2*>(&out[(size_t)(r0 + 8) * ODIM + c0i]) = v1;
        }
    }
}

// ---------------- host ----------------
extern "C" void kernel_launch(void* const* d_in, const int* in_sizes, int n_in,
                              void* d_out, int out_size) {
    const float* x   = (const float*)d_in[0];   // [4096, 512]
    const float* var = (const float*)d_in[1];   // [4096, 64]
    const float* W   = (const float*)d_in[2];   // [64, 512, 512]
    const float* b1  = (const float*)d_in[3];   // [64, 512]
    float* out       = (float*)d_out;           // [4096, 512]

    {
        dim3 tb(32, 32), tg(IDIM / 32, NROWS / 32);
        transpose_x<<<tg, tb>>>(x);
    }
    {
        dim3 tb(32, 32), tg(IDIM, ODIM / 32);
        prep_w<<<tg, tb>>>(W);
    }
    {
        dim3 tb(32, 32);
        prep_b<<<ODIM / 32, tb>>>(b1);
    }

    cudaFuncSetAttribute(mlp_mma, cudaFuncAttributeMaxDynamicSharedMemorySize, SMEM_TOTAL);
    dim3 grid(ODIM / BN, NROWS / BM);   // (8, 32) = 256 CTAs, 2 per SM
    mlp_mma<<<grid, NTH, SMEM_TOTAL>>>(var, out);
}

// round 12
// speedup vs baseline: 1.0817x; 1.0303x over previous
#include <cuda_runtime.h>
#include <cuda_fp16.h>
#include <cstdint>
#include <cstddef>

#define NROWS 4096
#define ODIM  512
#define IDIM  512
#define DDIM  64

#define BM 128
#define BN 64
#define NTH 256
#define NT_W 256            // W tiles (2 i each); tile 256 = bias
#define NSUP 128            // super-tiles of 2 W tiles

#define BPITCHB 272u                       // 68 words ≡ 4 mod 32 -> ldmatrix 8-row conflict-free
#define B_STAGE (64u * BPITCHB)            // 17408 B
#define NSTAGE 6
#define SMEM_TOTAL (int)(6u * B_STAGE)     // 104448 B -> 2 CTAs/SM (<=113KB each)

__device__ float  g_xT[IDIM * NROWS];                  // x transposed: [512][4096] fp32
__device__ __half g_Wt[(size_t)IDIM * ODIM * DDIM];    // W re-laid: [i][o][d] fp16
__device__ __half g_bt[ODIM * DDIM];                   // b1 re-laid: [o][d] fp16

// ---------------- helpers ----------------
__device__ __forceinline__ uint32_t smem_u32(const void* p) {
    uint32_t a;
    asm("{ .reg .u64 t; cvta.to.shared.u64 t, %1; cvt.u32.u64 %0, t; }" : "=r"(a) : "l"(p));
    return a;
}
__device__ __forceinline__ uint32_t f2h2(float f) {   // (h,h) packed fp16x2
    uint32_t r;
    asm("{ .reg .b16 h; cvt.rn.f16.f32 h, %1; mov.b32 %0, {h, h}; }" : "=r"(r) : "f"(f));
    return r;
}
__device__ __forceinline__ uint32_t pack2(float lo, float hi) {
    __half2 h = __floats2half2_rn(lo, hi);
    return *reinterpret_cast<uint32_t*>(&h);
}
#define CP_ASYNC16(dst, src) \
    asm volatile("cp.async.cg.shared.global [%0], [%1], 16;" :: "r"(dst), "l"(src) : "memory")
#define CP_COMMIT() asm volatile("cp.async.commit_group;" ::: "memory")
#define CP_WAIT2()  asm volatile("cp.async.wait_group 2;" ::: "memory")

#define LDMX4(r0, r1, r2, r3, a) \
    asm volatile("ldmatrix.sync.aligned.m8n8.x4.shared.b16 {%0,%1,%2,%3}, [%4];" \
        : "=r"(r0), "=r"(r1), "=r"(r2), "=r"(r3) : "r"(a))
#define HMUL2(d, a, b) asm("mul.rn.f16x2 %0, %1, %2;" : "=r"(d) : "r"(a), "r"(b))

__device__ __forceinline__ void mma_f16_16816(float& c0, float& c1, float& c2, float& c3,
                                              uint32_t a0, uint32_t a1, uint32_t a2, uint32_t a3,
                                              uint32_t b0, uint32_t b1) {
    asm volatile(
        "mma.sync.aligned.m16n8k16.row.col.f32.f16.f16.f32 "
        "{%0,%1,%2,%3}, {%4,%5,%6,%7}, {%8,%9}, {%0,%1,%2,%3};"
        : "+f"(c0), "+f"(c1), "+f"(c2), "+f"(c3)
        : "r"(a0), "r"(a1), "r"(a2), "r"(a3), "r"(b0), "r"(b1));
}

// ---------------- prepass kernels ----------------
__global__ void __launch_bounds__(1024) transpose_x(const float* __restrict__ x) {
    __shared__ float t[32][33];
    const int bi = blockIdx.x * 32;
    const int bn = blockIdx.y * 32;
    t[threadIdx.y][threadIdx.x] = x[(size_t)(bn + threadIdx.y) * IDIM + bi + threadIdx.x];
    __syncthreads();
    g_xT[(size_t)(bi + threadIdx.y) * NROWS + bn + threadIdx.x] = t[threadIdx.x][threadIdx.y];
}

// W[d][i][o] fp32 -> g_Wt[i][o][d] fp16
__global__ void __launch_bounds__(1024) prep_w(const float* __restrict__ W) {
    __shared__ float sm[32][65];
    const int i  = blockIdx.x;
    const int ob = blockIdx.y * 32;
    const int tx = threadIdx.x, ty = threadIdx.y;
#pragma unroll
    for (int k = 0; k < 2; ++k) {
        int d = ty + k * 32;
        sm[tx][d] = W[(size_t)d * IDIM * ODIM + (size_t)i * ODIM + ob + tx];
    }
    __syncthreads();
    __half2 h = __floats2half2_rn(sm[ty][2 * tx], sm[ty][2 * tx + 1]);
    reinterpret_cast<__half2*>(g_Wt)[((size_t)i * ODIM + ob + ty) * 32 + tx] = h;
}

// b1[d][o] fp32 -> g_bt[o][d] fp16
__global__ void __launch_bounds__(1024) prep_b(const float* __restrict__ b1) {
    __shared__ float sm[32][65];
    const int ob = blockIdx.x * 32;
    const int tx = threadIdx.x, ty = threadIdx.y;
#pragma unroll
    for (int k = 0; k < 2; ++k) {
        int d = ty + k * 32;
        sm[tx][d] = b1[(size_t)d * ODIM + ob + tx];
    }
    __syncthreads();
    __half2 h = __floats2half2_rn(sm[ty][2 * tx], sm[ty][2 * tx + 1]);
    reinterpret_cast<__half2*>(g_bt)[(size_t)(ob + ty) * 32 + tx] = h;
}

// ---------------- main kernel: super-tiles (2 tiles / barrier), 6-stage ring ----------------
__global__ void __launch_bounds__(NTH, 2) mlp_mma(
    const float* __restrict__ var,
    float* __restrict__ out)
{
    extern __shared__ __align__(128) uint8_t smem[];
    const uint32_t s0 = smem_u32(smem);

    const int tid  = threadIdx.x;
    const int lane = tid & 31;
    const int w    = tid >> 5;
    const int rowBase = blockIdx.y * BM;
    const int colBase = blockIdx.x * BN;

    const int wm = (w & 3) * 32;    // warp m-base (4 warps over M)
    const int wn = (w >> 2) * 32;   // warp n-base (2 warps over N)
    const int c  = lane & 3;
    const int g  = lane >> 2;

    // ----- this thread's 4 fragment rows -----
    int xr[4];
#pragma unroll
    for (int rr = 0; rr < 4; ++rr)
        xr[rr] = rowBase + wm + (rr >> 1) * 16 + (rr & 1) * 8 + g;

    // ----- v fragments in registers, loaded ONCE -----
    uint32_t vh[4][4][2];
#pragma unroll
    for (int rr = 0; rr < 4; ++rr) {
        const float* vp = var + (size_t)xr[rr] * DDIM;
#pragma unroll
        for (int grp = 0; grp < 4; ++grp) {
            float2 p0 = *reinterpret_cast<const float2*>(vp + grp * 16 + 2 * c);
            float2 p1 = *reinterpret_cast<const float2*>(vp + grp * 16 + 8 + 2 * c);
            vh[rr][grp][0] = pack2(p0.x, p0.y);
            vh[rr][grp][1] = pack2(p1.x, p1.y);
        }
    }

    // ----- ldmatrix per-lane base -----
    const int q = lane >> 3, r8 = lane & 7;
    const uint32_t bRowLd = (uint32_t)(wn + ((q >> 1) << 3) + r8) * BPITCHB
                          + (uint32_t)(q & 1) * 16u;

    // ----- B loader (cp.async) -----
    const int bo = tid >> 2;
    const int ci = tid & 3;
    auto issueB = [&](int t) {
        if (t <= NT_W) {
            const uint32_t dstBase = s0 + (uint32_t)(t % NSTAGE) * B_STAGE + (uint32_t)bo * BPITCHB;
            if (t < NT_W) {
                const __half* p0 = g_Wt + ((size_t)(2 * t) * ODIM + colBase + bo) * DDIM;
                const __half* p1 = p0 + (size_t)ODIM * DDIM;
#pragma unroll
                for (int cc = 0; cc < 2; ++cc) {
                    uint32_t ch = (uint32_t)(ci + cc * 4);
                    CP_ASYNC16(dstBase + ch * 16u,        p0 + ch * 8);
                    CP_ASYNC16(dstBase + 128u + ch * 16u, p1 + ch * 8);
                }
            } else {    // bias: k 0..63 only (other half never read)
                const __half* p0 = g_bt + (size_t)(colBase + bo) * DDIM;
#pragma unroll
                for (int cc = 0; cc < 2; ++cc) {
                    uint32_t ch = (uint32_t)(ci + cc * 4);
                    CP_ASYNC16(dstBase + ch * 16u, p0 + ch * 8);
                }
            }
        }
        CP_COMMIT();   // empty group when t > NT_W keeps wait accounting exact
    };
    auto loadX4 = [&](int jj, float (&dst)[4][4]) {
#pragma unroll
        for (int s = 0; s < 4; ++s)
#pragma unroll
            for (int rr = 0; rr < 4; ++rr)
                dst[s][rr] = __ldg(&g_xT[(size_t)(4 * jj + s) * NROWS + xr[rr]]);
    };

    float C[2][4][4];
#pragma unroll
    for (int mt = 0; mt < 2; ++mt)
#pragma unroll
        for (int nt = 0; nt < 4; ++nt)
#pragma unroll
            for (int qq = 0; qq < 4; ++qq) C[mt][nt][qq] = 0.0f;

    // ----- prologue: 4 tile-groups in flight, x for super-tile 0 -----
    issueB(0); issueB(1); issueB(2); issueB(3);
    float xc[4][4];
    loadX4(0, xc);

    // ----- mainloop: 128 super-tiles, one barrier each -----
    for (int j = 0; j < NSUP; ++j) {
        CP_WAIT2();            // groups 2j, 2j+1 landed
        __syncthreads();       // stages (2j+4)%6, (2j+5)%6 free (read 2 tiles ago)

        issueB(2 * j + 4);
        issueB(2 * j + 5);

        uint32_t xh[4][4];
#pragma unroll
        for (int s = 0; s < 4; ++s)
#pragma unroll
            for (int rr = 0; rr < 4; ++rr)
                xh[s][rr] = f2h2(xc[s][rr]);
        if (j < NSUP - 1) loadX4(j + 1, xc);

        const uint32_t base0 = s0 + (uint32_t)((2 * j) % NSTAGE) * B_STAGE + bRowLd;
        const uint32_t base1 = s0 + (uint32_t)((2 * j + 1) % NSTAGE) * B_STAGE + bRowLd;

        // continuous 16-step stream, B double-buffered across both tiles
        uint32_t bb[2][4][2];
        LDMX4(bb[0][0][0], bb[0][0][1], bb[0][1][0], bb[0][1][1], base0);
        LDMX4(bb[0][2][0], bb[0][2][1], bb[0][3][0], bb[0][3][1], base0 + 16u * BPITCHB);

#pragma unroll
        for (int kk = 0; kk < 16; ++kk) {
            const int half = kk >> 3, loc = kk & 7;
            const int grp = loc >> 1, il = half * 2 + (loc & 1);
            const int cur = kk & 1;
            if (kk < 15) {
                const int nk = kk + 1, nh = nk >> 3, nl = nk & 7;
                const int nks = (nl & 1) * 4 + (nl >> 1);
                const uint32_t nb = (nh ? base1 : base0) + (uint32_t)nks * 32u;
                const int nxt = cur ^ 1;
                LDMX4(bb[nxt][0][0], bb[nxt][0][1], bb[nxt][1][0], bb[nxt][1][1], nb);
                LDMX4(bb[nxt][2][0], bb[nxt][2][1], bb[nxt][3][0], bb[nxt][3][1],
                      nb + 16u * BPITCHB);
            }
            uint32_t a[2][4];
#pragma unroll
            for (int mt = 0; mt < 2; ++mt) {
                HMUL2(a[mt][0], xh[il][mt * 2 + 0], vh[mt * 2 + 0][grp][0]);
                HMUL2(a[mt][1], xh[il][mt * 2 + 1], vh[mt * 2 + 1][grp][0]);
                HMUL2(a[mt][2], xh[il][mt * 2 + 0], vh[mt * 2 + 0][grp][1]);
                HMUL2(a[mt][3], xh[il][mt * 2 + 1], vh[mt * 2 + 1][grp][1]);
            }
#pragma unroll
            for (int mt = 0; mt < 2; ++mt)
#pragma unroll
                for (int nt = 0; nt < 4; ++nt)
                    mma_f16_16816(C[mt][nt][0], C[mt][nt][1], C[mt][nt][2], C[mt][nt][3],
                                  a[mt][0], a[mt][1], a[mt][2], a[mt][3],
                                  bb[cur][nt][0], bb[cur][nt][1]);
        }
    }

    // ----- bias tile (t = 256, stage 256 % 6 = 4): only its 4 real k-steps -----
    {
        CP_WAIT2();            // group 256 landed
        __syncthreads();
        const uint32_t baseB = s0 + (uint32_t)(NT_W % NSTAGE) * B_STAGE + bRowLd;
        const uint32_t one = f2h2(1.0f);
#pragma unroll
        for (int grp = 0; grp < 4; ++grp) {
            uint32_t b[4][2];
            LDMX4(b[0][0], b[0][1], b[1][0], b[1][1], baseB + (uint32_t)grp * 32u);
            LDMX4(b[2][0], b[2][1], b[3][0], b[3][1],
                  baseB + (uint32_t)grp * 32u + 16u * BPITCHB);
            uint32_t a[2][4];
#pragma unroll
            for (int mt = 0; mt < 2; ++mt) {
                HMUL2(a[mt][0], one, vh[mt * 2 + 0][grp][0]);
                HMUL2(a[mt][1], one, vh[mt * 2 + 1][grp][0]);
                HMUL2(a[mt][2], one, vh[mt * 2 + 0][grp][1]);
                HMUL2(a[mt][3], one, vh[mt * 2 + 1][grp][1]);
            }
#pragma unroll
            for (int mt = 0; mt < 2; ++mt)
#pragma unroll
                for (int nt = 0; nt < 4; ++nt)
                    mma_f16_16816(C[mt][nt][0], C[mt][nt][1], C[mt][nt][2], C[mt][nt][3],
                                  a[mt][0], a[mt][1], a[mt][2], a[mt][3],
                                  b[nt][0], b[nt][1]);
        }
    }

    // ----- epilogue -----
#pragma unroll
    for (int mt = 0; mt < 2; ++mt) {
        const int r0 = rowBase + wm + mt * 16 + g;
#pragma unroll
        for (int nt = 0; nt < 4; ++nt) {
            const int c0i = colBase + wn + nt * 8 + c * 2;
            float2 v0, v1;
            v0.x = C[mt][nt][0]; v0.y = C[mt][nt][1];
            v1.x = C[mt][nt][2]; v1.y = C[mt][nt][3];
            *reinterpret_cast<float2*>(&out[(size_t)r0 * ODIM + c0i]) = v0;
            *reinterpret_cast<float2*>(&out[(size_t)(r0 + 8) * ODIM + c0i]) = v1;
        }
    }
}

// ---------------- host ----------------
extern "C" void kernel_launch(void* const* d_in, const int* in_sizes, int n_in,
                              void* d_out, int out_size) {
    const float* x   = (const float*)d_in[0];   // [4096, 512]
    const float* var = (const float*)d_in[1];   // [4096, 64]
    const float* W   = (const float*)d_in[2];   // [64, 512, 512]
    const float* b1  = (const float*)d_in[3];   // [64, 512]
    float* out       = (float*)d_out;           // [4096, 512]

    {
        dim3 tb(32, 32), tg(IDIM / 32, NROWS / 32);
        transpose_x<<<tg, tb>>>(x);
    }
    {
        dim3 tb(32, 32), tg(IDIM, ODIM / 32);
        prep_w<<<tg, tb>>>(W);
    }
    {
        dim3 tb(32, 32);
        prep_b<<<ODIM / 32, tb>>>(b1);
    }

    cudaFuncSetAttribute(mlp_mma, cudaFuncAttributeMaxDynamicSharedMemorySize, SMEM_TOTAL);
    dim3 grid(ODIM / BN, NROWS / BM);   // (8, 32) = 256 CTAs, 2 per SM
    mlp_mma<<<grid, NTH, SMEM_TOTAL>>>(var, out);
}